// round 12
// baseline (speedup 1.0000x reference)
#include <cuda_runtime.h>
#include <cuda_bf16.h>

#define N_STEPS   256
#define N_LORS    65536
#define IMG_ELEMS (128*128*128)
#define N_CUBES   (64*64*64)

#define RCP_VOX (1.0f / 2.34375f)
#define VOX     2.34375f

// Image and accumulator in sector-tiled (2x2x2 cube) layout:
// one 32B sector = one 2x2x2 voxel cube. Slot order within cube:
// ((x&1)<<2) | ((y&1)<<1) | (z&1)  -> slots (2k, 2k+1) are z-pairs, 8B-aligned.
__device__ float g_img_cube[IMG_ELEMS];
__device__ float g_acc_cube[IMG_ELEMS];

__device__ __forceinline__ int cube_flat(int ix, int iy, int iz) {
    const int c = (((ix >> 1) << 6) + (iy >> 1)) * 64 + (iz >> 1);
    return (c << 3) + ((ix & 1) << 2) + ((iy & 1) << 1) + (iz & 1);
}

// div.rn(x, VOX) via correctly-rounded reciprocal + one Markstein FMA step
// (matches IEEE division; flip probability <1e-9/coord — see earlier rounds).
__device__ __forceinline__ float div_vox(float x) {
    float q = __fmul_rn(x, RCP_VOX);
    q = __fmaf_rn(__fmaf_rn(-VOX, q, x), RCP_VOX, q);
    return q;
}

// ---------------------------------------------------------------------------
// Kernel 1: coalesced remap image -> cube layout + zero accumulator.
// ---------------------------------------------------------------------------
__global__ void remap_kernel(const float* __restrict__ img) {
    const int c  = blockIdx.x * blockDim.x + threadIdx.x;   // cube id
    const int cx = c >> 12, cy = (c >> 6) & 63, cz = c & 63;
    const int base = cx * 32768 + cy * 256 + cz * 2;

    const float2 a = *(const float2*)(img + base);               // (0,0,*)
    const float2 b = *(const float2*)(img + base + 128);         // (0,1,*)
    const float2 d = *(const float2*)(img + base + 16384);       // (1,0,*)
    const float2 e = *(const float2*)(img + base + 16384 + 128); // (1,1,*)

    float4* dst = (float4*)(g_img_cube + (c << 3));
    dst[0] = make_float4(a.x, a.y, b.x, b.y);
    dst[1] = make_float4(d.x, d.y, e.x, e.y);

    float4* az = (float4*)(g_acc_cube + (c << 3));
    az[0] = make_float4(0.f, 0.f, 0.f, 0.f);
    az[1] = make_float4(0.f, 0.f, 0.f, 0.f);
}

// ---------------------------------------------------------------------------
// Kernel 2: warp-per-LOR, lane = consecutive step within each 32-step chunk.
//   Backprojection: one RED per same-voxel run, EXCEPT adjacent runs forming
//   a z-pair (flats f, f+1 with f even) merge into one red.global.v2.f32 —
//   fewer lanes, identical bytes. Iterations remain fully independent.
// ---------------------------------------------------------------------------
__global__ __launch_bounds__(256)
void trace_kernel(const float* __restrict__ xl,
                  const float* __restrict__ yl,
                  const float* __restrict__ zl) {
    const int warp = blockIdx.x * (blockDim.x >> 5) + (threadIdx.x >> 5);
    const int lane = threadIdx.x & 31;
    const int set  = warp >> 16;          // 0,1,2
    const int lor  = warp & (N_LORS - 1);

    const float* lors = (set == 0) ? xl : (set == 1) ? yl : zl;
    const float* L = lors + 7 * lor;

    const float p1x = __ldg(L + 0), p1y = __ldg(L + 1), p1z = __ldg(L + 2);
    const float dx = __fadd_rn(__ldg(L + 3), -p1x);
    const float dy = __fadd_rn(__ldg(L + 4), -p1y);
    const float dz = __fadd_rn(__ldg(L + 5), -p1z);
    const float meas = __ldg(L + 6);
    const float seg = sqrtf(dx*dx + dy*dy + dz*dz) * (1.0f / N_STEPS);

    int flats[8];

    // exact: all t are multiples of 2^-9
    float t = ((float)lane + 0.5f) * (1.0f / N_STEPS);

    #pragma unroll
    for (int it = 0; it < 8; it++) {
        const float px = __fadd_rn(p1x, __fmul_rn(t, dx));
        const float py = __fadd_rn(p1y, __fmul_rn(t, dy));
        const float pz = __fadd_rn(p1z, __fmul_rn(t, dz));
        const int ix = __float2int_rd(div_vox(__fadd_rn(px, 150.0f)));
        const int iy = __float2int_rd(div_vox(__fadd_rn(py, 150.0f)));
        const int iz = __float2int_rd(div_vox(__fadd_rn(pz, 150.0f)));
        const bool inb = ((unsigned)ix < 128u) & ((unsigned)iy < 128u) &
                         ((unsigned)iz < 128u);
        flats[it] = inb ? cube_flat(ix, iy, iz) : -1;
        t = __fadd_rn(t, 0.125f);
    }

    // ---- forward projection: 8 independent gathers ----
    float s = 0.f;
    #pragma unroll
    for (int it = 0; it < 8; it++) {
        const int f = flats[it];
        s += (f >= 0) ? __ldg(g_img_cube + f) : 0.f;
    }

    #pragma unroll
    for (int o = 16; o > 0; o >>= 1)
        s += __shfl_xor_sync(0xffffffffu, s, o);

    const float proj = s * seg;
    const float w = meas / (proj + 1e-8f) * seg;   // ratio * seg

    // ---- backprojection with z-pair merging ----
    #pragma unroll
    for (int it = 0; it < 8; it++) {
        const int f = flats[it];
        const int fprev = __shfl_up_sync(0xffffffffu, f, 1);
        const bool head = (lane == 0) || (f != fprev);
        const unsigned b = __ballot_sync(0xffffffffu, head);

        const unsigned rest = (b >> lane) >> 1;             // heads after me
        const int cnt = rest ? __ffs(rest) : (32 - lane);   // my run length

        // next head's flat/cnt (valid when rest != 0)
        const int nextLane = (lane + cnt) & 31;
        const int nextf   = __shfl_sync(0xffffffffu, f,   nextLane);
        const int nextcnt = __shfl_sync(0xffffffffu, cnt, nextLane);

        // previous head's flat (to detect that I've been absorbed)
        const unsigned prevMask = b & ((1u << lane) - 1u);
        const int prevLane = prevMask ? (31 - __clz(prevMask)) : 0;
        const int prevf = __shfl_sync(0xffffffffu, f, prevLane);

        if (head && f >= 0) {
            const bool absorbed = prevMask && ((prevf & 1) == 0) &&
                                  (prevf + 1 == f);
            if (!absorbed) {
                const bool merge = rest && ((f & 1) == 0) && (nextf == f + 1);
                if (merge) {
                    atomicAdd((float2*)(g_acc_cube + f),
                              make_float2(w * (float)cnt, w * (float)nextcnt));
                } else {
                    atomicAdd(g_acc_cube + f, w * (float)cnt);
                }
            }
        }
    }
}

// ---------------------------------------------------------------------------
// Kernel 3: out = image / (eff + eps) * acc.  One thread per cube.
// ---------------------------------------------------------------------------
__global__ void finalize_kernel(const float* __restrict__ img,
                                const float* __restrict__ eff,
                                float* __restrict__ out) {
    const int c  = blockIdx.x * blockDim.x + threadIdx.x;   // cube id
    const int cx = c >> 12, cy = (c >> 6) & 63, cz = c & 63;
    const int base = cx * 32768 + cy * 256 + cz * 2;

    const float4* av = (const float4*)(g_acc_cube + (c << 3));
    const float4 a0 = av[0];
    const float4 a1 = av[1];

    #pragma unroll
    for (int k = 0; k < 4; k++) {
        const int off = ((k >> 1) ? 16384 : 0) + ((k & 1) ? 128 : 0);
        const float2 im = *(const float2*)(img + base + off);
        const float2 ef = *(const float2*)(eff + base + off);
        const float ax = (k == 0) ? a0.x : (k == 1) ? a0.z : (k == 2) ? a1.x : a1.z;
        const float ay = (k == 0) ? a0.y : (k == 1) ? a0.w : (k == 2) ? a1.y : a1.w;
        float2 o;
        o.x = im.x / (ef.x + 1e-8f) * ax;
        o.y = im.y / (ef.y + 1e-8f) * ay;
        *(float2*)(out + base + off) = o;
    }
}

extern "C" void kernel_launch(void* const* d_in, const int* in_sizes, int n_in,
                              void* d_out, int out_size) {
    const float* image = (const float*)d_in[0];
    const float* eff   = (const float*)d_in[1];
    const float* xl    = (const float*)d_in[2];
    const float* yl    = (const float*)d_in[3];
    const float* zl    = (const float*)d_in[4];
    float* out = (float*)d_out;

    remap_kernel<<<N_CUBES / 256, 256>>>(image);

    const int total_warps = 3 * N_LORS;          // one warp per LOR
    trace_kernel<<<total_warps / 8, 256>>>(xl, yl, zl);

    finalize_kernel<<<N_CUBES / 256, 256>>>(image, eff, out);
}

// round 13
// speedup vs baseline: 1.1438x; 1.1438x over previous
#include <cuda_runtime.h>
#include <cuda_bf16.h>

#define N_STEPS   256
#define N_LORS    65536
#define IMG_ELEMS (128*128*128)

#define RCP_VOX (1.0f / 2.34375f)
#define VOX     2.34375f

// Image and accumulator in sector-tiled (2x2x2 cube) layout:
// one 32B sector = one 2x2x2 voxel cube. Slot order within cube:
// ((x&1)<<2) | ((y&1)<<1) | (z&1).
__device__ float g_img_cube[IMG_ELEMS];
__device__ float g_acc_cube[IMG_ELEMS];

__device__ __forceinline__ int cube_flat(int ix, int iy, int iz) {
    const int c = (((ix >> 1) << 6) + (iy >> 1)) * 64 + (iz >> 1);
    return (c << 3) + ((ix & 1) << 2) + ((iy & 1) << 1) + (iz & 1);
}

// div.rn(x, VOX) via correctly-rounded reciprocal + one Markstein FMA step
// (matches IEEE division; flip probability <1e-9/coord — see earlier rounds).
__device__ __forceinline__ float div_vox(float x) {
    float q = __fmul_rn(x, RCP_VOX);
    q = __fmaf_rn(__fmaf_rn(-VOX, q, x), RCP_VOX, q);
    return q;
}

// ---------------------------------------------------------------------------
// Kernel 1: remap image -> cube layout + zero accumulator.
// One thread per z-PAIR of cubes: 4 coalesced float4 reads, 64B-contiguous
// cube writes (4 float4) + 64B acc zeroing.
// ---------------------------------------------------------------------------
__global__ void remap_kernel(const float* __restrict__ img) {
    const int t  = blockIdx.x * blockDim.x + threadIdx.x;   // pair id
    const int cx = t >> 11, cy = (t >> 5) & 63, pz = t & 31;
    const int base = cx * 32768 + cy * 256 + pz * 4;        // natural idx
    const int c0 = (((cx << 6) + cy) << 6) + (pz << 1);     // first cube id

    const float4 a = *(const float4*)(img + base);           // (0,0,z0..z3)
    const float4 b = *(const float4*)(img + base + 128);     // (0,1,*)
    const float4 d = *(const float4*)(img + base + 16384);   // (1,0,*)
    const float4 e = *(const float4*)(img + base + 16512);   // (1,1,*)

    float4* dst = (float4*)(g_img_cube + (c0 << 3));
    dst[0] = make_float4(a.x, a.y, b.x, b.y);   // cube c0, slots 0-3
    dst[1] = make_float4(d.x, d.y, e.x, e.y);   // cube c0, slots 4-7
    dst[2] = make_float4(a.z, a.w, b.z, b.w);   // cube c0+1, slots 0-3
    dst[3] = make_float4(d.z, d.w, e.z, e.w);   // cube c0+1, slots 4-7

    float4* az = (float4*)(g_acc_cube + (c0 << 3));
    const float4 z = make_float4(0.f, 0.f, 0.f, 0.f);
    az[0] = z; az[1] = z; az[2] = z; az[3] = z;
}

// ---------------------------------------------------------------------------
// Kernel 2: warp-per-LOR, lane = consecutive step within each 32-step chunk.
//   Backprojection: one scalar 4B RED per same-voxel run, with runs merged
//   ACROSS iteration boundaries via a dependence-free extension chain
//   (all flats precomputed -> tail flats / lead counts / ext computable with
//   constant register indices; nothing loop-carried).
// ---------------------------------------------------------------------------
__global__ __launch_bounds__(256)
void trace_kernel(const float* __restrict__ xl,
                  const float* __restrict__ yl,
                  const float* __restrict__ zl) {
    const unsigned FULL = 0xffffffffu;
    const int warp = blockIdx.x * (blockDim.x >> 5) + (threadIdx.x >> 5);
    const int lane = threadIdx.x & 31;
    const int set  = warp >> 16;          // 0,1,2
    const int lor  = warp & (N_LORS - 1);

    const float* lors = (set == 0) ? xl : (set == 1) ? yl : zl;
    const float* L = lors + 7 * lor;

    const float p1x = __ldg(L + 0), p1y = __ldg(L + 1), p1z = __ldg(L + 2);
    const float dx = __fadd_rn(__ldg(L + 3), -p1x);
    const float dy = __fadd_rn(__ldg(L + 4), -p1y);
    const float dz = __fadd_rn(__ldg(L + 5), -p1z);
    const float meas = __ldg(L + 6);
    const float seg = sqrtf(dx*dx + dy*dy + dz*dz) * (1.0f / N_STEPS);

    int flats[8];

    // exact: all t are multiples of 2^-9
    float t = ((float)lane + 0.5f) * (1.0f / N_STEPS);

    #pragma unroll
    for (int it = 0; it < 8; it++) {
        const float px = __fadd_rn(p1x, __fmul_rn(t, dx));
        const float py = __fadd_rn(p1y, __fmul_rn(t, dy));
        const float pz = __fadd_rn(p1z, __fmul_rn(t, dz));
        const int ix = __float2int_rd(div_vox(__fadd_rn(px, 150.0f)));
        const int iy = __float2int_rd(div_vox(__fadd_rn(py, 150.0f)));
        const int iz = __float2int_rd(div_vox(__fadd_rn(pz, 150.0f)));
        const bool inb = ((unsigned)ix < 128u) & ((unsigned)iy < 128u) &
                         ((unsigned)iz < 128u);
        flats[it] = inb ? cube_flat(ix, iy, iz) : -1;
        t = __fadd_rn(t, 0.125f);
    }

    // ---- forward projection: 8 independent gathers ----
    float s = 0.f;
    #pragma unroll
    for (int it = 0; it < 8; it++) {
        const int f = flats[it];
        s += (f >= 0) ? __ldg(g_img_cube + f) : 0.f;
    }

    #pragma unroll
    for (int o = 16; o > 0; o >>= 1)
        s += __shfl_xor_sync(FULL, s, o);

    const float proj = s * seg;
    const float w = meas / (proj + 1e-8f) * seg;   // ratio * seg

    // ---- boundary-merge metadata (all warp-uniform, constant indices) ----
    int tail[8];                       // flat of lane 31 per iteration
    #pragma unroll
    for (int it = 0; it < 8; it++)
        tail[it] = __shfl_sync(FULL, flats[it], 31);

    int lead[8];                       // leading lanes of it matching tail[it-1]
    lead[0] = 0;
    #pragma unroll
    for (int it = 1; it < 8; it++) {
        const unsigned bm = __ballot_sync(FULL, flats[it] == tail[it - 1]);
        const unsigned nm = ~bm;
        lead[it] = nm ? (__ffs(nm) - 1) : 32;
    }

    int ext[8];                        // steps absorbed after this iteration's tail
    ext[7] = 0;
    #pragma unroll
    for (int it = 6; it >= 0; it--)
        ext[it] = lead[it + 1] + ((lead[it + 1] == 32) ? ext[it + 1] : 0);

    // ---- backprojection: one scalar RED per merged run ----
    #pragma unroll
    for (int it = 0; it < 8; it++) {
        const int f = flats[it];
        const int fprev = __shfl_up_sync(FULL, f, 1);
        const bool head = (lane == 0) ? (it == 0 || f != tail[it - 1])
                                      : (f != fprev);
        const unsigned b = __ballot_sync(FULL, head);
        if (head && f >= 0) {
            const unsigned rest = (b >> lane) >> 1;   // heads after me
            const int cnt = rest ? __ffs(rest) : (32 - lane + ext[it]);
            atomicAdd(g_acc_cube + f, w * (float)cnt);
        }
    }
}

// ---------------------------------------------------------------------------
// Kernel 3: out = image / (eff + eps) * acc.  One thread per z-pair of cubes:
// 64B-contiguous acc reads, float4 img/eff/out accesses.
// ---------------------------------------------------------------------------
__global__ void finalize_kernel(const float* __restrict__ img,
                                const float* __restrict__ eff,
                                float* __restrict__ out) {
    const int t  = blockIdx.x * blockDim.x + threadIdx.x;   // pair id
    const int cx = t >> 11, cy = (t >> 5) & 63, pz = t & 31;
    const int base = cx * 32768 + cy * 256 + pz * 4;
    const int c0 = (((cx << 6) + cy) << 6) + (pz << 1);

    const float4* av = (const float4*)(g_acc_cube + (c0 << 3));
    const float4 a0 = av[0];   // cube c0 slots 0-3
    const float4 a1 = av[1];   // cube c0 slots 4-7
    const float4 a2 = av[2];   // cube c0+1 slots 0-3
    const float4 a3 = av[3];   // cube c0+1 slots 4-7

    #pragma unroll
    for (int k = 0; k < 4; k++) {
        const int off = ((k >> 1) ? 16384 : 0) + ((k & 1) ? 128 : 0);
        const float4 im = *(const float4*)(img + base + off);
        const float4 ef = *(const float4*)(eff + base + off);
        float4 ac;
        if      (k == 0) ac = make_float4(a0.x, a0.y, a2.x, a2.y);
        else if (k == 1) ac = make_float4(a0.z, a0.w, a2.z, a2.w);
        else if (k == 2) ac = make_float4(a1.x, a1.y, a3.x, a3.y);
        else             ac = make_float4(a1.z, a1.w, a3.z, a3.w);
        float4 o;
        o.x = im.x / (ef.x + 1e-8f) * ac.x;
        o.y = im.y / (ef.y + 1e-8f) * ac.y;
        o.z = im.z / (ef.z + 1e-8f) * ac.z;
        o.w = im.w / (ef.w + 1e-8f) * ac.w;
        *(float4*)(out + base + off) = o;
    }
}

extern "C" void kernel_launch(void* const* d_in, const int* in_sizes, int n_in,
                              void* d_out, int out_size) {
    const float* image = (const float*)d_in[0];
    const float* eff   = (const float*)d_in[1];
    const float* xl    = (const float*)d_in[2];
    const float* yl    = (const float*)d_in[3];
    const float* zl    = (const float*)d_in[4];
    float* out = (float*)d_out;

    remap_kernel<<<(64*64*32) / 256, 256>>>(image);

    const int total_warps = 3 * N_LORS;          // one warp per LOR
    trace_kernel<<<total_warps / 8, 256>>>(xl, yl, zl);

    finalize_kernel<<<(64*64*32) / 256, 256>>>(image, eff, out);
}

// round 14
// speedup vs baseline: 1.3457x; 1.1764x over previous
#include <cuda_runtime.h>
#include <cuda_bf16.h>

#define N_STEPS   256
#define N_LORS    65536
#define IMG_ELEMS (128*128*128)
#define N_CUBES   (64*64*64)

#define RCP_VOX (1.0f / 2.34375f)
#define VOX     2.34375f

// Image and accumulator in sector-tiled (2x2x2 cube) layout:
// one 32B sector = one 2x2x2 voxel cube. Slot order within cube:
// ((x&1)<<2) | ((y&1)<<1) | (z&1).
__device__ float g_img_cube[IMG_ELEMS];
__device__ float g_acc_cube[IMG_ELEMS];

__device__ __forceinline__ int cube_flat(int ix, int iy, int iz) {
    const int c = (((ix >> 1) << 6) + (iy >> 1)) * 64 + (iz >> 1);
    return (c << 3) + ((ix & 1) << 2) + ((iy & 1) << 1) + (iz & 1);
}

// div.rn(x, VOX) via correctly-rounded reciprocal + one Markstein FMA step
// (matches IEEE division; flip probability <1e-9/coord — see earlier rounds).
__device__ __forceinline__ float div_vox(float x) {
    float q = __fmul_rn(x, RCP_VOX);
    q = __fmaf_rn(__fmaf_rn(-VOX, q, x), RCP_VOX, q);
    return q;
}

// ---------------------------------------------------------------------------
// Kernel 1: coalesced remap image -> cube layout + zero accumulator.
// (r10/r11 version — best measured: 7.5-8.1 us, one thread per cube.)
// ---------------------------------------------------------------------------
__global__ void remap_kernel(const float* __restrict__ img) {
    const int c  = blockIdx.x * blockDim.x + threadIdx.x;   // cube id
    const int cx = c >> 12, cy = (c >> 6) & 63, cz = c & 63;
    const int base = cx * 32768 + cy * 256 + cz * 2;

    const float2 a = *(const float2*)(img + base);               // (0,0,*)
    const float2 b = *(const float2*)(img + base + 128);         // (0,1,*)
    const float2 d = *(const float2*)(img + base + 16384);       // (1,0,*)
    const float2 e = *(const float2*)(img + base + 16384 + 128); // (1,1,*)

    float4* dst = (float4*)(g_img_cube + (c << 3));
    dst[0] = make_float4(a.x, a.y, b.x, b.y);
    dst[1] = make_float4(d.x, d.y, e.x, e.y);

    float4* az = (float4*)(g_acc_cube + (c << 3));
    az[0] = make_float4(0.f, 0.f, 0.f, 0.f);
    az[1] = make_float4(0.f, 0.f, 0.f, 0.f);
}

// ---------------------------------------------------------------------------
// Kernel 2: warp-per-LOR (r11 body, best measured). PDL: everything up to
// the first g_img_cube read is independent of remap, so it runs BEFORE
// cudaGridDependencySynchronize() and overlaps remap's drain.
// ---------------------------------------------------------------------------
__global__ __launch_bounds__(256)
void trace_kernel(const float* __restrict__ xl,
                  const float* __restrict__ yl,
                  const float* __restrict__ zl) {
    const unsigned FULL = 0xffffffffu;
    const int warp = blockIdx.x * (blockDim.x >> 5) + (threadIdx.x >> 5);
    const int lane = threadIdx.x & 31;
    const int set  = warp >> 16;          // 0,1,2
    const int lor  = warp & (N_LORS - 1);

    const float* lors = (set == 0) ? xl : (set == 1) ? yl : zl;
    const float* L = lors + 7 * lor;

    const float p1x = __ldg(L + 0), p1y = __ldg(L + 1), p1z = __ldg(L + 2);
    const float dx = __fadd_rn(__ldg(L + 3), -p1x);
    const float dy = __fadd_rn(__ldg(L + 4), -p1y);
    const float dz = __fadd_rn(__ldg(L + 5), -p1z);
    const float meas = __ldg(L + 6);
    const float seg = sqrtf(dx*dx + dy*dy + dz*dz) * (1.0f / N_STEPS);

    int flats[8];

    // exact: all t are multiples of 2^-9
    float t = ((float)lane + 0.5f) * (1.0f / N_STEPS);

    #pragma unroll
    for (int it = 0; it < 8; it++) {
        const float px = __fadd_rn(p1x, __fmul_rn(t, dx));
        const float py = __fadd_rn(p1y, __fmul_rn(t, dy));
        const float pz = __fadd_rn(p1z, __fmul_rn(t, dz));
        const int ix = __float2int_rd(div_vox(__fadd_rn(px, 150.0f)));
        const int iy = __float2int_rd(div_vox(__fadd_rn(py, 150.0f)));
        const int iz = __float2int_rd(div_vox(__fadd_rn(pz, 150.0f)));
        const bool inb = ((unsigned)ix < 128u) & ((unsigned)iy < 128u) &
                         ((unsigned)iz < 128u);
        flats[it] = inb ? cube_flat(ix, iy, iz) : -1;
        t = __fadd_rn(t, 0.125f);
    }

    // wait for remap (img_cube populated, acc_cube zeroed)
    cudaGridDependencySynchronize();

    // ---- forward projection: 8 independent gathers ----
    float s = 0.f;
    #pragma unroll
    for (int it = 0; it < 8; it++) {
        const int f = flats[it];
        s += (f >= 0) ? __ldg(g_img_cube + f) : 0.f;
    }

    #pragma unroll
    for (int o = 16; o > 0; o >>= 1)
        s += __shfl_xor_sync(FULL, s, o);

    const float proj = s * seg;
    const float w = meas / (proj + 1e-8f) * seg;   // ratio * seg

    // ---- backprojection: one scalar atomic per contiguous same-voxel run --
    #pragma unroll
    for (int it = 0; it < 8; it++) {
        const int f = flats[it];
        const int fprev = __shfl_up_sync(FULL, f, 1);
        const bool head = (lane == 0) || (f != fprev);
        const unsigned b = __ballot_sync(FULL, head);
        if (head && f >= 0) {
            const unsigned rest = (b >> lane) >> 1;   // heads after me
            const int cnt = rest ? __ffs(rest) : (32 - lane);
            atomicAdd(g_acc_cube + f, w * (float)cnt);
        }
    }
}

// ---------------------------------------------------------------------------
// Kernel 3: out = image / (eff + eps) * acc  (r11 body + PDL: img/eff loads
// and the divisions happen BEFORE the dependency sync, overlapping trace's
// tail; only the acc_cube read waits.)
// ---------------------------------------------------------------------------
__global__ void finalize_kernel(const float* __restrict__ img,
                                const float* __restrict__ eff,
                                float* __restrict__ out) {
    const int c  = blockIdx.x * blockDim.x + threadIdx.x;   // cube id
    const int cx = c >> 12, cy = (c >> 6) & 63, cz = c & 63;
    const int base = cx * 32768 + cy * 256 + cz * 2;

    // pre-dependency work: load img/eff, compute img/(eff+eps)
    float rx[4], ry[4];
    #pragma unroll
    for (int k = 0; k < 4; k++) {
        const int off = ((k >> 1) ? 16384 : 0) + ((k & 1) ? 128 : 0);
        const float2 im = *(const float2*)(img + base + off);
        const float2 ef = *(const float2*)(eff + base + off);
        rx[k] = im.x / (ef.x + 1e-8f);
        ry[k] = im.y / (ef.y + 1e-8f);
    }

    // wait for trace (acc_cube complete)
    cudaGridDependencySynchronize();

    const float4* av = (const float4*)(g_acc_cube + (c << 3));
    const float4 a0 = av[0];   // slots 0..3
    const float4 a1 = av[1];   // slots 4..7

    #pragma unroll
    for (int k = 0; k < 4; k++) {
        const int off = ((k >> 1) ? 16384 : 0) + ((k & 1) ? 128 : 0);
        const float ax = (k == 0) ? a0.x : (k == 1) ? a0.z : (k == 2) ? a1.x : a1.z;
        const float ay = (k == 0) ? a0.y : (k == 1) ? a0.w : (k == 2) ? a1.y : a1.w;
        float2 o;
        o.x = rx[k] * ax;
        o.y = ry[k] * ay;
        *(float2*)(out + base + off) = o;
    }
}

extern "C" void kernel_launch(void* const* d_in, const int* in_sizes, int n_in,
                              void* d_out, int out_size) {
    const float* image = (const float*)d_in[0];
    const float* eff   = (const float*)d_in[1];
    const float* xl    = (const float*)d_in[2];
    const float* yl    = (const float*)d_in[3];
    const float* zl    = (const float*)d_in[4];
    float* out = (float*)d_out;

    // 1) remap (plain launch)
    remap_kernel<<<N_CUBES / 256, 256>>>(image);

    // PDL attribute: secondary may begin as primary drains; it must call
    // cudaGridDependencySynchronize() before consuming primary's output.
    cudaLaunchAttribute attr[1];
    attr[0].id = cudaLaunchAttributeProgrammaticStreamSerialization;
    attr[0].val.programmaticStreamSerializationAllowed = 1;

    // 2) trace (PDL w.r.t. remap)
    {
        cudaLaunchConfig_t cfg = {};
        cfg.gridDim  = dim3((3 * N_LORS) / 8, 1, 1);   // one warp per LOR
        cfg.blockDim = dim3(256, 1, 1);
        cfg.stream = 0;
        cfg.attrs = attr;
        cfg.numAttrs = 1;
        cudaLaunchKernelEx(&cfg, trace_kernel, xl, yl, zl);
    }

    // 3) finalize (PDL w.r.t. trace)
    {
        cudaLaunchConfig_t cfg = {};
        cfg.gridDim  = dim3(N_CUBES / 256, 1, 1);
        cfg.blockDim = dim3(256, 1, 1);
        cfg.stream = 0;
        cfg.attrs = attr;
        cfg.numAttrs = 1;
        cudaLaunchKernelEx(&cfg, finalize_kernel, image, eff, out);
    }
}

// round 15
// speedup vs baseline: 1.3660x; 1.0151x over previous
#include <cuda_runtime.h>
#include <cuda_bf16.h>

#define N_STEPS   256
#define N_LORS    65536
#define IMG_ELEMS (128*128*128)
#define N_CUBES   (64*64*64)

#define RCP_VOX (1.0f / 2.34375f)
#define VOX     2.34375f

// Image and accumulator in sector-tiled (2x2x2 cube) layout:
// one 32B sector = one 2x2x2 voxel cube. Slot order within cube:
// ((x&1)<<2) | ((y&1)<<1) | (z&1).
__device__ float g_img_cube[IMG_ELEMS];
__device__ float g_acc_cube[IMG_ELEMS];

__device__ __forceinline__ int cube_flat(int ix, int iy, int iz) {
    const int c = (((ix >> 1) << 6) + (iy >> 1)) * 64 + (iz >> 1);
    return (c << 3) + ((ix & 1) << 2) + ((iy & 1) << 1) + (iz & 1);
}

// div.rn(x, VOX) via correctly-rounded reciprocal + one Markstein FMA step
// (matches IEEE division; flip probability <1e-9/coord — see earlier rounds).
__device__ __forceinline__ float div_vox(float x) {
    float q = __fmul_rn(x, RCP_VOX);
    q = __fmaf_rn(__fmaf_rn(-VOX, q, x), RCP_VOX, q);
    return q;
}

// ---------------------------------------------------------------------------
// Kernel 1: coalesced remap image -> cube layout + zero accumulator.
// Triggers programmatic launch of the dependent (trace) IMMEDIATELY: trace's
// pre-sync prologue (LOR loads + index math) overlaps this kernel entirely.
// ---------------------------------------------------------------------------
__global__ void remap_kernel(const float* __restrict__ img) {
    cudaTriggerProgrammaticLaunchCompletion();

    const int c  = blockIdx.x * blockDim.x + threadIdx.x;   // cube id
    const int cx = c >> 12, cy = (c >> 6) & 63, cz = c & 63;
    const int base = cx * 32768 + cy * 256 + cz * 2;

    const float2 a = *(const float2*)(img + base);               // (0,0,*)
    const float2 b = *(const float2*)(img + base + 128);         // (0,1,*)
    const float2 d = *(const float2*)(img + base + 16384);       // (1,0,*)
    const float2 e = *(const float2*)(img + base + 16384 + 128); // (1,1,*)

    float4* dst = (float4*)(g_img_cube + (c << 3));
    dst[0] = make_float4(a.x, a.y, b.x, b.y);
    dst[1] = make_float4(d.x, d.y, e.x, e.y);

    float4* az = (float4*)(g_acc_cube + (c << 3));
    az[0] = make_float4(0.f, 0.f, 0.f, 0.f);
    az[1] = make_float4(0.f, 0.f, 0.f, 0.f);
}

// ---------------------------------------------------------------------------
// Kernel 2: warp-per-LOR (r11 hot loop, frozen). Pre-sync prologue runs
// under PDL overlap with remap; triggers finalize's programmatic launch so
// finalize's img/eff loads overlap this kernel's tail.
// ---------------------------------------------------------------------------
__global__ __launch_bounds__(256)
void trace_kernel(const float* __restrict__ xl,
                  const float* __restrict__ yl,
                  const float* __restrict__ zl) {
    cudaTriggerProgrammaticLaunchCompletion();

    const unsigned FULL = 0xffffffffu;
    const int warp = blockIdx.x * (blockDim.x >> 5) + (threadIdx.x >> 5);
    const int lane = threadIdx.x & 31;
    const int set  = warp >> 16;          // 0,1,2
    const int lor  = warp & (N_LORS - 1);

    const float* lors = (set == 0) ? xl : (set == 1) ? yl : zl;
    const float* L = lors + 7 * lor;

    const float p1x = __ldg(L + 0), p1y = __ldg(L + 1), p1z = __ldg(L + 2);
    const float dx = __fadd_rn(__ldg(L + 3), -p1x);
    const float dy = __fadd_rn(__ldg(L + 4), -p1y);
    const float dz = __fadd_rn(__ldg(L + 5), -p1z);
    const float meas = __ldg(L + 6);
    const float seg = sqrtf(dx*dx + dy*dy + dz*dz) * (1.0f / N_STEPS);

    int flats[8];

    // exact: all t are multiples of 2^-9
    float t = ((float)lane + 0.5f) * (1.0f / N_STEPS);

    #pragma unroll
    for (int it = 0; it < 8; it++) {
        const float px = __fadd_rn(p1x, __fmul_rn(t, dx));
        const float py = __fadd_rn(p1y, __fmul_rn(t, dy));
        const float pz = __fadd_rn(p1z, __fmul_rn(t, dz));
        const int ix = __float2int_rd(div_vox(__fadd_rn(px, 150.0f)));
        const int iy = __float2int_rd(div_vox(__fadd_rn(py, 150.0f)));
        const int iz = __float2int_rd(div_vox(__fadd_rn(pz, 150.0f)));
        const bool inb = ((unsigned)ix < 128u) & ((unsigned)iy < 128u) &
                         ((unsigned)iz < 128u);
        flats[it] = inb ? cube_flat(ix, iy, iz) : -1;
        t = __fadd_rn(t, 0.125f);
    }

    // wait for remap (img_cube populated, acc_cube zeroed)
    cudaGridDependencySynchronize();

    // ---- forward projection: 8 independent gathers ----
    float s = 0.f;
    #pragma unroll
    for (int it = 0; it < 8; it++) {
        const int f = flats[it];
        s += (f >= 0) ? __ldg(g_img_cube + f) : 0.f;
    }

    #pragma unroll
    for (int o = 16; o > 0; o >>= 1)
        s += __shfl_xor_sync(FULL, s, o);

    const float proj = s * seg;
    const float w = meas / (proj + 1e-8f) * seg;   // ratio * seg

    // ---- backprojection: one scalar atomic per contiguous same-voxel run --
    #pragma unroll
    for (int it = 0; it < 8; it++) {
        const int f = flats[it];
        const int fprev = __shfl_up_sync(FULL, f, 1);
        const bool head = (lane == 0) || (f != fprev);
        const unsigned b = __ballot_sync(FULL, head);
        if (head && f >= 0) {
            const unsigned rest = (b >> lane) >> 1;   // heads after me
            const int cnt = rest ? __ffs(rest) : (32 - lane);
            atomicAdd(g_acc_cube + f, w * (float)cnt);
        }
    }
}

// ---------------------------------------------------------------------------
// Kernel 3: out = image / (eff + eps) * acc. Pre-sync: img/eff loads and
// divisions (overlap trace's tail under PDL); post-sync: acc gather + store.
// ---------------------------------------------------------------------------
__global__ void finalize_kernel(const float* __restrict__ img,
                                const float* __restrict__ eff,
                                float* __restrict__ out) {
    const int c  = blockIdx.x * blockDim.x + threadIdx.x;   // cube id
    const int cx = c >> 12, cy = (c >> 6) & 63, cz = c & 63;
    const int base = cx * 32768 + cy * 256 + cz * 2;

    // pre-dependency work: load img/eff, compute img/(eff+eps)
    float rx[4], ry[4];
    #pragma unroll
    for (int k = 0; k < 4; k++) {
        const int off = ((k >> 1) ? 16384 : 0) + ((k & 1) ? 128 : 0);
        const float2 im = *(const float2*)(img + base + off);
        const float2 ef = *(const float2*)(eff + base + off);
        rx[k] = im.x / (ef.x + 1e-8f);
        ry[k] = im.y / (ef.y + 1e-8f);
    }

    // wait for trace (acc_cube complete)
    cudaGridDependencySynchronize();

    const float4* av = (const float4*)(g_acc_cube + (c << 3));
    const float4 a0 = av[0];   // slots 0..3
    const float4 a1 = av[1];   // slots 4..7

    #pragma unroll
    for (int k = 0; k < 4; k++) {
        const int off = ((k >> 1) ? 16384 : 0) + ((k & 1) ? 128 : 0);
        const float ax = (k == 0) ? a0.x : (k == 1) ? a0.z : (k == 2) ? a1.x : a1.z;
        const float ay = (k == 0) ? a0.y : (k == 1) ? a0.w : (k == 2) ? a1.y : a1.w;
        float2 o;
        o.x = rx[k] * ax;
        o.y = ry[k] * ay;
        *(float2*)(out + base + off) = o;
    }
}

extern "C" void kernel_launch(void* const* d_in, const int* in_sizes, int n_in,
                              void* d_out, int out_size) {
    const float* image = (const float*)d_in[0];
    const float* eff   = (const float*)d_in[1];
    const float* xl    = (const float*)d_in[2];
    const float* yl    = (const float*)d_in[3];
    const float* zl    = (const float*)d_in[4];
    float* out = (float*)d_out;

    // 1) remap (plain launch; triggers PDL for trace at its start)
    remap_kernel<<<N_CUBES / 256, 256>>>(image);

    cudaLaunchAttribute attr[1];
    attr[0].id = cudaLaunchAttributeProgrammaticStreamSerialization;
    attr[0].val.programmaticStreamSerializationAllowed = 1;

    // 2) trace (PDL w.r.t. remap)
    {
        cudaLaunchConfig_t cfg = {};
        cfg.gridDim  = dim3((3 * N_LORS) / 8, 1, 1);   // one warp per LOR
        cfg.blockDim = dim3(256, 1, 1);
        cfg.stream = 0;
        cfg.attrs = attr;
        cfg.numAttrs = 1;
        cudaLaunchKernelEx(&cfg, trace_kernel, xl, yl, zl);
    }

    // 3) finalize (PDL w.r.t. trace)
    {
        cudaLaunchConfig_t cfg = {};
        cfg.gridDim  = dim3(N_CUBES / 256, 1, 1);
        cfg.blockDim = dim3(256, 1, 1);
        cfg.stream = 0;
        cfg.attrs = attr;
        cfg.numAttrs = 1;
        cudaLaunchKernelEx(&cfg, finalize_kernel, image, eff, out);
    }
}